// round 2
// baseline (speedup 1.0000x reference)
#include <cuda_runtime.h>

// WindowAttention fused kernel, packed-fp32 (f32x2 / FFMA2) version.
// One block per window. All intermediates in shared memory.
//   1. load xc = [cls ; x[beta]] into ROW-PAIRED layout + mask
//   2. QKV GEMM with f32x2 accumulators over row pairs
//   3. per-head attention (warp h = head h), f32x2 over head-dim pairs
//   4. proj GEMM (f32x2 row pairs) -> d_out
//
// d_out: [0, B*C) cls outputs ; [B*C, B*C + B*49*C) token outputs.

#define NTOK 50
#define NPAIR 25
#define DIM 256
#define BATCH 2048
#define NTHREADS 256
#define ATTN_SCALE 0.17677669529663689f   // 32^-0.5

// s_pair: [pair][k] float2, stride 516 floats per pair (258 float2)
#define PSF 516
// s_qkv: unpaired rows, stride 772 floats (772 % 32 == 4 -> <=4-way conflicts)
#define QS 772

#define SMEM_FLOATS (NPAIR * PSF + NTOK * QS + 2500)   // 54000
#define SMEM_BYTES (SMEM_FLOATS * 4)                   // 216000

typedef unsigned long long ull;

#define FMA2(acc, a, b) asm("fma.rn.f32x2 %0, %1, %2, %0;" : "+l"(acc) : "l"(a), "l"(b))
#define PACK2(d, s)     asm("mov.b64 %0, {%1, %1};"      : "=l"(d)   : "f"(s))
#define UNPACK2(x, y, v) asm("mov.b64 {%0, %1}, %2;"     : "=f"(x), "=f"(y) : "l"(v))

__global__ void __launch_bounds__(NTHREADS, 1)
win_attn_f32x2_kernel(const float* __restrict__ x,
                      const float* __restrict__ mask,
                      const float* __restrict__ cls_tok,
                      const float* __restrict__ qkv_w,
                      const float* __restrict__ qkv_b,
                      const float* __restrict__ proj_w,
                      const float* __restrict__ proj_b,
                      float* __restrict__ out)
{
    extern __shared__ float smem[];
    float* s_pair = smem;                    // NPAIR * PSF (xc paired, later attn-out paired)
    float* s_qkv  = smem + NPAIR * PSF;      // NTOK * QS : per row [q(256) k(256) v(256)]
    float* s_mask = s_qkv + NTOK * QS;       // 2500

    const int t    = threadIdx.x;
    const int beta = blockIdx.x;

    // ---- Phase 1: load xc into paired layout, load mask ----
    {
        const float* xb = x + (size_t)beta * 49 * DIM;
        // 25 pairs x 64 col-groups of 4
        for (int idx = t; idx < NPAIR * 64; idx += NTHREADS) {
            int p = idx >> 6;
            int c = (idx & 63) << 2;
            int rA = 2 * p, rB = 2 * p + 1;
            float4 a = (rA == 0) ? *(const float4*)&cls_tok[c]
                                 : *(const float4*)&xb[(size_t)(rA - 1) * DIM + c];
            float4 b = *(const float4*)&xb[(size_t)(rB - 1) * DIM + c];
            float* dst = &s_pair[p * PSF + 2 * c];
            dst[0] = a.x; dst[1] = b.x; dst[2] = a.y; dst[3] = b.y;
            dst[4] = a.z; dst[5] = b.z; dst[6] = a.w; dst[7] = b.w;
        }
        const float* mrow = mask + (size_t)(beta & 63) * 2500;
        for (int idx = t; idx < 2500; idx += NTHREADS)
            s_mask[idx] = mrow[idx];
    }
    __syncthreads();

    // ---- Phase 2: QKV GEMM, f32x2 over row pairs ----
    #pragma unroll 1
    for (int pass = 0; pass < 3; ++pass) {
        const int c = pass * NTHREADS + t;
        ull acc[NPAIR];
        #pragma unroll
        for (int p = 0; p < NPAIR; ++p) acc[p] = 0ull;

        const float* wc = qkv_w + c;
        float w0 = wc[0];
        float w1 = wc[768];
        #pragma unroll 1
        for (int k = 0; k < DIM; k += 2) {
            const int kn = (k + 2) & 255;          // wraps harmlessly on last iter
            float nw0 = wc[(size_t)kn * 768];
            float nw1 = wc[(size_t)(kn + 1) * 768];
            ull w0p, w1p;
            PACK2(w0p, w0);
            PACK2(w1p, w1);
            const float* xrow = &s_pair[2 * k];
            #pragma unroll
            for (int p = 0; p < NPAIR; ++p) {
                ulonglong2 xv = *(const ulonglong2*)&xrow[p * PSF];
                FMA2(acc[p], xv.x, w0p);
                FMA2(acc[p], xv.y, w1p);
            }
            w0 = nw0; w1 = nw1;
        }
        const float b = qkv_b[c];
        const float m = (pass == 0) ? ATTN_SCALE : 1.0f;   // pre-scale q
        #pragma unroll
        for (int p = 0; p < NPAIR; ++p) {
            float f0, f1;
            UNPACK2(f0, f1, acc[p]);
            s_qkv[(2 * p) * QS + c]     = (f0 + b) * m;
            s_qkv[(2 * p + 1) * QS + c] = (f1 + b) * m;
        }
    }
    __syncthreads();

    // ---- Phase 3: attention (warp h = head h; lane owns rows lane, lane+32) ----
    {
        const int h    = t >> 5;
        const int lane = t & 31;
        const int hoff = h * 32;

        for (int r = lane; r < NTOK; r += 32) {
            // q row into 16 packed regs
            ull q2[16];
            #pragma unroll
            for (int dq = 0; dq < 8; ++dq) {
                ulonglong2 v = *(const ulonglong2*)&s_qkv[r * QS + hoff + 4 * dq];
                q2[2 * dq]     = v.x;
                q2[2 * dq + 1] = v.y;
            }

            // scores
            float s[NTOK];
            #pragma unroll
            for (int j = 0; j < NTOK; ++j) {
                ull a2 = 0ull;
                const float* krow = &s_qkv[j * QS + 256 + hoff];
                #pragma unroll
                for (int dq = 0; dq < 8; ++dq) {
                    ulonglong2 kv = *(const ulonglong2*)&krow[4 * dq];
                    FMA2(a2, q2[2 * dq], kv.x);
                    FMA2(a2, q2[2 * dq + 1], kv.y);
                }
                float a0, a1;
                UNPACK2(a0, a1, a2);
                s[j] = a0 + a1 + s_mask[r * NTOK + j];
            }

            // softmax
            float mx = s[0];
            #pragma unroll
            for (int j = 1; j < NTOK; ++j) mx = fmaxf(mx, s[j]);
            float sum = 0.0f;
            #pragma unroll
            for (int j = 0; j < NTOK; ++j) { s[j] = __expf(s[j] - mx); sum += s[j]; }
            const float inv = 1.0f / sum;

            // out = P @ V, packed over head-dim pairs
            ull o2[16];
            #pragma unroll
            for (int e = 0; e < 16; ++e) o2[e] = 0ull;
            #pragma unroll
            for (int j = 0; j < NTOK; ++j) {
                ull p2;
                PACK2(p2, s[j]);
                const float* vrow = &s_qkv[j * QS + 512 + hoff];
                #pragma unroll
                for (int dq = 0; dq < 8; ++dq) {
                    ulonglong2 vv = *(const ulonglong2*)&vrow[4 * dq];
                    FMA2(o2[2 * dq], vv.x, p2);
                    FMA2(o2[2 * dq + 1], vv.y, p2);
                }
            }
            // write normalized output into paired buffer:
            // float d at s_pair[(r>>1)*PSF + 2*(hoff+d) + (r&1)]
            float* base = &s_pair[(r >> 1) * PSF + 2 * hoff + (r & 1)];
            #pragma unroll
            for (int e = 0; e < 16; ++e) {
                float f0, f1;
                UNPACK2(f0, f1, o2[e]);    // head-dims 2e, 2e+1
                base[4 * e]     = f0 * inv;
                base[4 * e + 2] = f1 * inv;
            }
        }
    }
    __syncthreads();

    // ---- Phase 4: proj GEMM, f32x2 over row pairs, + store ----
    {
        const int c = t;
        ull acc[NPAIR];
        #pragma unroll
        for (int p = 0; p < NPAIR; ++p) acc[p] = 0ull;

        const float* wc = proj_w + c;
        float w0 = wc[0];
        float w1 = wc[256];
        #pragma unroll 1
        for (int k = 0; k < DIM; k += 2) {
            const int kn = (k + 2) & 255;
            float nw0 = wc[(size_t)kn * 256];
            float nw1 = wc[(size_t)(kn + 1) * 256];
            ull w0p, w1p;
            PACK2(w0p, w0);
            PACK2(w1p, w1);
            const float* xrow = &s_pair[2 * k];
            #pragma unroll
            for (int p = 0; p < NPAIR; ++p) {
                ulonglong2 xv = *(const ulonglong2*)&xrow[p * PSF];
                FMA2(acc[p], xv.x, w0p);
                FMA2(acc[p], xv.y, w1p);
            }
            w0 = nw0; w1 = nw1;
        }
        const float pb = proj_b[c];
        float* tok = out + (size_t)BATCH * DIM;

        // pair 0: rows 0 (cls) and 1 (token 0)
        {
            float f0, f1;
            UNPACK2(f0, f1, acc[0]);
            out[(size_t)beta * DIM + c] = f0 + pb;
            tok[((size_t)beta * 49 + 0) * DIM + c] = f1 + pb;
        }
        #pragma unroll
        for (int p = 1; p < NPAIR; ++p) {
            float f0, f1;
            UNPACK2(f0, f1, acc[p]);
            tok[((size_t)beta * 49 + (2 * p - 1)) * DIM + c] = f0 + pb;
            tok[((size_t)beta * 49 + (2 * p))     * DIM + c] = f1 + pb;
        }
    }
}

extern "C" void kernel_launch(void* const* d_in, const int* in_sizes, int n_in,
                              void* d_out, int out_size)
{
    const float* x      = (const float*)d_in[0];
    const float* mask   = (const float*)d_in[1];
    const float* cls    = (const float*)d_in[2];
    const float* qkv_w  = (const float*)d_in[3];
    const float* qkv_b  = (const float*)d_in[4];
    const float* proj_w = (const float*)d_in[5];
    const float* proj_b = (const float*)d_in[6];
    float* out = (float*)d_out;

    cudaFuncSetAttribute(win_attn_f32x2_kernel,
                         cudaFuncAttributeMaxDynamicSharedMemorySize, SMEM_BYTES);

    win_attn_f32x2_kernel<<<BATCH, NTHREADS, SMEM_BYTES>>>(
        x, mask, cls, qkv_w, qkv_b, proj_w, proj_b, out);
}

// round 3
// speedup vs baseline: 1.5959x; 1.5959x over previous
#include <cuda_runtime.h>

// WindowAttention fused kernel, packed-fp32 (f32x2 / FFMA2) version.
// One block per window. All intermediates in shared memory.
//   1. load xc = [cls ; x[beta]] into ROW-PAIRED layout + mask
//   2. QKV GEMM with f32x2 accumulators over row pairs
//   3. per-head attention (warp h = head h), f32x2 over head-dim pairs
//   4. proj GEMM (f32x2 row pairs) -> d_out
//
// d_out: [0, B*C) cls outputs ; [B*C, B*C + B*49*C) token outputs.

#define NTOK 50
#define NPAIR 25
#define DIM 256
#define BATCH 2048
#define NTHREADS 256
#define ATTN_SCALE 0.17677669529663689f   // 32^-0.5

// s_pair: [pair][k] float2, stride 516 floats per pair (258 float2)
#define PSF 516
// s_qkv: unpaired rows, stride 772 floats (772 % 32 == 4 -> <=4-way conflicts)
#define QS 772

#define SMEM_FLOATS (NPAIR * PSF + NTOK * QS + 2500)   // 54000
#define SMEM_BYTES (SMEM_FLOATS * 4)                   // 216000

typedef unsigned long long ull;

#define FMA2(acc, a, b) asm("fma.rn.f32x2 %0, %1, %2, %0;" : "+l"(acc) : "l"(a), "l"(b))
#define PACK2(d, s)     asm("mov.b64 %0, {%1, %1};"      : "=l"(d)   : "f"(s))
#define UNPACK2(x, y, v) asm("mov.b64 {%0, %1}, %2;"     : "=f"(x), "=f"(y) : "l"(v))

__global__ void __launch_bounds__(NTHREADS, 1)
win_attn_f32x2_kernel(const float* __restrict__ x,
                      const float* __restrict__ mask,
                      const float* __restrict__ cls_tok,
                      const float* __restrict__ qkv_w,
                      const float* __restrict__ qkv_b,
                      const float* __restrict__ proj_w,
                      const float* __restrict__ proj_b,
                      float* __restrict__ out)
{
    extern __shared__ float smem[];
    float* s_pair = smem;                    // NPAIR * PSF (xc paired, later attn-out paired)
    float* s_qkv  = smem + NPAIR * PSF;      // NTOK * QS : per row [q(256) k(256) v(256)]
    float* s_mask = s_qkv + NTOK * QS;       // 2500

    const int t    = threadIdx.x;
    const int beta = blockIdx.x;

    // ---- Phase 1: load xc into paired layout, load mask ----
    {
        const float* xb = x + (size_t)beta * 49 * DIM;
        // 25 pairs x 64 col-groups of 4
        for (int idx = t; idx < NPAIR * 64; idx += NTHREADS) {
            int p = idx >> 6;
            int c = (idx & 63) << 2;
            int rA = 2 * p, rB = 2 * p + 1;
            float4 a = (rA == 0) ? *(const float4*)&cls_tok[c]
                                 : *(const float4*)&xb[(size_t)(rA - 1) * DIM + c];
            float4 b = *(const float4*)&xb[(size_t)(rB - 1) * DIM + c];
            float* dst = &s_pair[p * PSF + 2 * c];
            dst[0] = a.x; dst[1] = b.x; dst[2] = a.y; dst[3] = b.y;
            dst[4] = a.z; dst[5] = b.z; dst[6] = a.w; dst[7] = b.w;
        }
        const float* mrow = mask + (size_t)(beta & 63) * 2500;
        for (int idx = t; idx < 2500; idx += NTHREADS)
            s_mask[idx] = mrow[idx];
    }
    __syncthreads();

    // ---- Phase 2: QKV GEMM, f32x2 over row pairs ----
    #pragma unroll 1
    for (int pass = 0; pass < 3; ++pass) {
        const int c = pass * NTHREADS + t;
        ull acc[NPAIR];
        #pragma unroll
        for (int p = 0; p < NPAIR; ++p) acc[p] = 0ull;

        const float* wc = qkv_w + c;
        float w0 = wc[0];
        float w1 = wc[768];
        #pragma unroll 1
        for (int k = 0; k < DIM; k += 2) {
            const int kn = (k + 2) & 255;          // wraps harmlessly on last iter
            float nw0 = wc[(size_t)kn * 768];
            float nw1 = wc[(size_t)(kn + 1) * 768];
            ull w0p, w1p;
            PACK2(w0p, w0);
            PACK2(w1p, w1);
            const float* xrow = &s_pair[2 * k];
            #pragma unroll
            for (int p = 0; p < NPAIR; ++p) {
                ulonglong2 xv = *(const ulonglong2*)&xrow[p * PSF];
                FMA2(acc[p], xv.x, w0p);
                FMA2(acc[p], xv.y, w1p);
            }
            w0 = nw0; w1 = nw1;
        }
        const float b = qkv_b[c];
        const float m = (pass == 0) ? ATTN_SCALE : 1.0f;   // pre-scale q
        #pragma unroll
        for (int p = 0; p < NPAIR; ++p) {
            float f0, f1;
            UNPACK2(f0, f1, acc[p]);
            s_qkv[(2 * p) * QS + c]     = (f0 + b) * m;
            s_qkv[(2 * p + 1) * QS + c] = (f1 + b) * m;
        }
    }
    __syncthreads();

    // ---- Phase 3: attention (warp h = head h; lane owns rows lane, lane+32) ----
    {
        const int h    = t >> 5;
        const int lane = t & 31;
        const int hoff = h * 32;

        for (int r = lane; r < NTOK; r += 32) {
            // q row into 16 packed regs
            ull q2[16];
            #pragma unroll
            for (int dq = 0; dq < 8; ++dq) {
                ulonglong2 v = *(const ulonglong2*)&s_qkv[r * QS + hoff + 4 * dq];
                q2[2 * dq]     = v.x;
                q2[2 * dq + 1] = v.y;
            }

            // scores
            float s[NTOK];
            #pragma unroll
            for (int j = 0; j < NTOK; ++j) {
                ull a2 = 0ull;
                const float* krow = &s_qkv[j * QS + 256 + hoff];
                #pragma unroll
                for (int dq = 0; dq < 8; ++dq) {
                    ulonglong2 kv = *(const ulonglong2*)&krow[4 * dq];
                    FMA2(a2, q2[2 * dq], kv.x);
                    FMA2(a2, q2[2 * dq + 1], kv.y);
                }
                float a0, a1;
                UNPACK2(a0, a1, a2);
                s[j] = a0 + a1 + s_mask[r * NTOK + j];
            }

            // softmax
            float mx = s[0];
            #pragma unroll
            for (int j = 1; j < NTOK; ++j) mx = fmaxf(mx, s[j]);
            float sum = 0.0f;
            #pragma unroll
            for (int j = 0; j < NTOK; ++j) { s[j] = __expf(s[j] - mx); sum += s[j]; }
            const float inv = 1.0f / sum;

            // out = P @ V, packed over head-dim pairs
            ull o2[16];
            #pragma unroll
            for (int e = 0; e < 16; ++e) o2[e] = 0ull;
            #pragma unroll
            for (int j = 0; j < NTOK; ++j) {
                ull p2;
                PACK2(p2, s[j]);
                const float* vrow = &s_qkv[j * QS + 512 + hoff];
                #pragma unroll
                for (int dq = 0; dq < 8; ++dq) {
                    ulonglong2 vv = *(const ulonglong2*)&vrow[4 * dq];
                    FMA2(o2[2 * dq], vv.x, p2);
                    FMA2(o2[2 * dq + 1], vv.y, p2);
                }
            }
            // write normalized output into paired buffer:
            // float d at s_pair[(r>>1)*PSF + 2*(hoff+d) + (r&1)]
            float* base = &s_pair[(r >> 1) * PSF + 2 * hoff + (r & 1)];
            #pragma unroll
            for (int e = 0; e < 16; ++e) {
                float f0, f1;
                UNPACK2(f0, f1, o2[e]);    // head-dims 2e, 2e+1
                base[4 * e]     = f0 * inv;
                base[4 * e + 2] = f1 * inv;
            }
        }
    }
    __syncthreads();

    // ---- Phase 4: proj GEMM, f32x2 over row pairs, + store ----
    {
        const int c = t;
        ull acc[NPAIR];
        #pragma unroll
        for (int p = 0; p < NPAIR; ++p) acc[p] = 0ull;

        const float* wc = proj_w + c;
        float w0 = wc[0];
        float w1 = wc[256];
        #pragma unroll 1
        for (int k = 0; k < DIM; k += 2) {
            const int kn = (k + 2) & 255;
            float nw0 = wc[(size_t)kn * 256];
            float nw1 = wc[(size_t)(kn + 1) * 256];
            ull w0p, w1p;
            PACK2(w0p, w0);
            PACK2(w1p, w1);
            const float* xrow = &s_pair[2 * k];
            #pragma unroll
            for (int p = 0; p < NPAIR; ++p) {
                ulonglong2 xv = *(const ulonglong2*)&xrow[p * PSF];
                FMA2(acc[p], xv.x, w0p);
                FMA2(acc[p], xv.y, w1p);
            }
            w0 = nw0; w1 = nw1;
        }
        const float pb = proj_b[c];
        float* tok = out + (size_t)BATCH * DIM;

        // pair 0: rows 0 (cls) and 1 (token 0)
        {
            float f0, f1;
            UNPACK2(f0, f1, acc[0]);
            out[(size_t)beta * DIM + c] = f0 + pb;
            tok[((size_t)beta * 49 + 0) * DIM + c] = f1 + pb;
        }
        #pragma unroll
        for (int p = 1; p < NPAIR; ++p) {
            float f0, f1;
            UNPACK2(f0, f1, acc[p]);
            tok[((size_t)beta * 49 + (2 * p - 1)) * DIM + c] = f0 + pb;
            tok[((size_t)beta * 49 + (2 * p))     * DIM + c] = f1 + pb;
        }
    }
}

extern "C" void kernel_launch(void* const* d_in, const int* in_sizes, int n_in,
                              void* d_out, int out_size)
{
    const float* x      = (const float*)d_in[0];
    const float* mask   = (const float*)d_in[1];
    const float* cls    = (const float*)d_in[2];
    const float* qkv_w  = (const float*)d_in[3];
    const float* qkv_b  = (const float*)d_in[4];
    const float* proj_w = (const float*)d_in[5];
    const float* proj_b = (const float*)d_in[6];
    float* out = (float*)d_out;

    cudaFuncSetAttribute(win_attn_f32x2_kernel,
                         cudaFuncAttributeMaxDynamicSharedMemorySize, SMEM_BYTES);

    win_attn_f32x2_kernel<<<BATCH, NTHREADS, SMEM_BYTES>>>(
        x, mask, cls, qkv_w, qkv_b, proj_w, proj_b, out);
}